// round 11
// baseline (speedup 1.0000x reference)
#include <cuda_runtime.h>

#define NL 4
#define TPB 128

typedef unsigned long long u64;

// ---- packed 2x f32 (Blackwell f32x2 pipe) ----
struct p2 { u64 v; };
struct p2x2 { p2 a, b; };

__device__ __forceinline__ p2 mk2(float lo, float hi) {
    p2 r; asm("mov.b64 %0, {%1,%2};" : "=l"(r.v) : "f"(lo), "f"(hi)); return r;
}
__device__ __forceinline__ void un2(p2 a, float& lo, float& hi) {
    asm("mov.b64 {%0,%1}, %2;" : "=f"(lo), "=f"(hi) : "l"(a.v));
}
__device__ __forceinline__ p2 fma2(p2 a, p2 b, p2 c) {
    p2 r; asm("fma.rn.f32x2 %0, %1, %2, %3;" : "=l"(r.v) : "l"(a.v), "l"(b.v), "l"(c.v)); return r;
}
__device__ __forceinline__ p2 mul2(p2 a, p2 b) {
    p2 r; asm("mul.rn.f32x2 %0, %1, %2;" : "=l"(r.v) : "l"(a.v), "l"(b.v)); return r;
}
__device__ __forceinline__ p2 add2(p2 a, p2 b) {
    p2 r; asm("add.rn.f32x2 %0, %1, %2;" : "=l"(r.v) : "l"(a.v), "l"(b.v)); return r;
}
__device__ __forceinline__ p2 neg2(p2 a) { p2 r; r.v = a.v ^ 0x8000000080000000ULL; return r; }

__device__ __forceinline__ float fast_tanh(float v) {
    float r; asm("tanh.approx.f32 %0, %1;" : "=f"(r) : "f"(v)); return r;
}

// ---- batch-invariant constants (global; staged to shared per block) ----
// float2 elements (both lanes equal), float4-friendly layout:
// [0:8)   w1 (pairs (0,1),(2,3),(4,5),(6,7))
// [8:12)  b1
// [12:20) w2 (row0: 12-15, row1: 16-19)
// [20:22) b2    [22:24) post_w    [24] post_b    [25] pad
// [26 + k*10 + j]  W(j,k), j=0..8, j=9 pad;  y(a0,a1) = sum_jk W(j,k) B_j(a0) B_k(a1)
//   basis: B_0=1, B_1=cos a, B_2=sin a, B_3=cos 2a, ... B_8=sin 4a
#define NC 116
__device__ __align__(16) float2 gStage[NC];
#define WBASE(k) (26 + (k) * 10)

// ---- scalar circuit helpers (setup only) ----
__device__ __forceinline__ void rx_s(float c, float s, float2& a, float2& b) {
    float2 na, nb;
    na.x = c * a.x + s * b.y; na.y = c * a.y - s * b.x;
    nb.x = c * b.x + s * a.y; nb.y = c * b.y - s * a.x;
    a = na; b = nb;
}
// SU(2): r00=(ar,ai), r01=(br,bi), r10=(-br,bi), r11=(ar,-ai)
__device__ __forceinline__ void rot_s(const float* M, float2& a, float2& b) {
    float ar = M[0], ai = M[1], br = M[2], bi = M[3];
    float2 na, nb;
    na.x = ar * a.x - ai * a.y + br * b.x - bi * b.y;
    na.y = ar * a.y + ai * a.x + br * b.y + bi * b.x;
    nb.x = -br * a.x - bi * a.y + ar * b.x + ai * b.y;
    nb.y = -br * a.y + bi * a.x + ar * b.y - ai * b.x;
    a = na; b = nb;
}

__global__ void setup_kernel(const float* __restrict__ w1, const float* __restrict__ b1,
                             const float* __restrict__ w2, const float* __restrict__ b2,
                             const float* __restrict__ qw,
                             const float* __restrict__ pw, const float* __restrict__ pb) {
    __shared__ float sM[8][4];      // ar, ai, br, bi per Rot matrix
    __shared__ float sY[81];        // y at grid nodes
    __shared__ float cT[9], sT[9];  // cos/sin(2*pi*r/9) table
    int tid = threadIdx.x;
    const float TH = 6.2831853071795864769f / 9.0f;

    if (tid < 25) {
        float v;
        if (tid < 8)       v = w1[tid];
        else if (tid < 12) v = b1[tid - 8];
        else if (tid < 20) v = w2[tid - 12];
        else if (tid < 22) v = b2[tid - 20];
        else if (tid < 24) v = pw[tid - 22];
        else               v = pb[0];
        gStage[tid] = make_float2(v, v);
    }
    // zero pads: element 25 and W row pads (j=9)
    if (tid >= 96 && tid < 105) gStage[WBASE(tid - 96) + 9] = make_float2(0.f, 0.f);
    if (tid == 105) gStage[25] = make_float2(0.f, 0.f);
    if (tid < 8) {
        const float* q = qw + tid * 3;
        float phi = q[0], th = q[1], om = q[2];
        float st, ct, sp, cp, sm, cm;
        sincosf(0.5f * th, &st, &ct);
        sincosf(0.5f * (phi + om), &sp, &cp);
        sincosf(0.5f * (phi - om), &sm, &cm);
        sM[tid][0] =  cp * ct;   // ar
        sM[tid][1] = -sp * ct;   // ai
        sM[tid][2] = -cm * st;   // br
        sM[tid][3] = -sm * st;   // bi
    }
    // 9-point trig table: the only angles the DFT needs (2*pi*r/9)
    if (tid >= 32 && tid < 41) {
        int r = tid - 32;
        float sv, cv;
        sincosf(TH * (float)r, &sv, &cv);
        cT[r] = cv; sT[r] = sv;
    }
    __syncthreads();

    // Phase B: simulate circuit at 81 grid nodes (exact bandlimited sampling)
    if (tid < 81) {
        int m = tid / 9, n = tid % 9;
        float c0, s0, c1, s1;
        __sincosf(0.5f * TH * (float)m, &s0, &c0);
        __sincosf(0.5f * TH * (float)n, &s1, &c1);
        float2 S00 = {1.f, 0.f}, S01 = {0.f, 0.f}, S10 = {0.f, 0.f}, S11 = {0.f, 0.f};
#pragma unroll
        for (int l = 0; l < NL; l++) {
            rx_s(c0, s0, S00, S10); rx_s(c0, s0, S01, S11);
            rx_s(c1, s1, S00, S01); rx_s(c1, s1, S10, S11);
            rot_s(sM[l * 2 + 0], S00, S10); rot_s(sM[l * 2 + 0], S01, S11);
            rot_s(sM[l * 2 + 1], S00, S01); rot_s(sM[l * 2 + 1], S10, S11);
            float2 t = S10; S10 = S11; S11 = t;   // CNOT(0,1)
            t = S01; S01 = S11; S11 = t;          // CNOT(1,0)
        }
        float p00 = S00.x * S00.x + S00.y * S00.y;
        float p01 = S01.x * S01.x + S01.y * S01.y;
        float p10 = S10.x * S10.x + S10.y * S10.y;
        float q0 = p00 + p01, q1 = p00 + p10;  // unitarity
        sY[tid] = pw[0] * q0 + pw[1] * q1 + pb[0];
    }
    __syncthreads();

    // Phase C: exact DFT projection onto the 9x9 trig basis (table lookups only)
    if (tid < 81) {
        int j = tid / 9, k = tid % 9;
        int tjf = (j + 1) / 2;   // frequency for j (unused when j==0)
        int tkf = (k + 1) / 2;
        float tk[9];
#pragma unroll
        for (int n = 0; n < 9; n++) {
            if (k == 0) tk[n] = 1.0f / 9.0f;
            else {
                int r = (n * tkf) % 9;
                tk[n] = (2.0f / 9.0f) * ((k & 1) ? cT[r] : sT[r]);
            }
        }
        float acc = 0.f;
#pragma unroll
        for (int m = 0; m < 9; m++) {
            float tj;
            if (j == 0) tj = 1.0f / 9.0f;
            else {
                int r = (m * tjf) % 9;
                tj = (2.0f / 9.0f) * ((j & 1) ? cT[r] : sT[r]);
            }
            float inner = 0.f;
#pragma unroll
            for (int n = 0; n < 9; n++) inner += tk[n] * sY[m * 9 + n];
            acc += tj * inner;
        }
        gStage[WBASE(k) + j] = make_float2(acc, acc);
    }
}

// u[0..7] = cos a, sin a, cos 2a, sin 2a, ..., cos 4a, sin 4a  (packed over 2 samples)
__device__ __forceinline__ void build_u(p2* u, p2 c, p2 s) {
    u[0] = c; u[1] = s;
    p2 d = add2(c, c);
    u[2] = fma2(d, c, mk2(-1.f, -1.f));
    u[3] = mul2(d, s);
    u[4] = fma2(d, u[2], neg2(c));
    u[5] = fma2(d, u[3], neg2(s));
    u[6] = fma2(d, u[4], neg2(u[2]));
    u[7] = fma2(d, u[5], neg2(u[3]));
}

__global__ __launch_bounds__(TPB) void hybrid_qnn_kernel(
    const float4* __restrict__ x4, float4* __restrict__ out4, int B4)
{
    __shared__ __align__(16) float2 sC[NC];
    int tid = threadIdx.x;
    if (tid < NC / 2) {   // 58 x LDG.128 / STS.128
        reinterpret_cast<float4*>(sC)[tid] =
            reinterpret_cast<const float4*>(gStage)[tid];
    }
    __syncthreads();

    int i = blockIdx.x * TPB + tid;
    if (i >= B4) return;

    const float4* C4 = reinterpret_cast<const float4*>(sC);
    const p2*     C2 = reinterpret_cast<const p2*>(sC);
    // load float2-elements (e, e+1) as one LDS.128; e must be even
    auto F4 = [&](int e) -> p2x2 {
        float4 t = C4[e >> 1];
        p2x2 r; r.a = mk2(t.x, t.y); r.b = mk2(t.z, t.w); return r;
    };

    // 4 samples per thread: 2 independent packed chains
    p2 u0[2][8], u1[2][8];
#pragma unroll
    for (int ch = 0; ch < 2; ch++) {
        float4 xv = x4[2 * i + ch];
        p2 X0 = mk2(xv.x, xv.z);
        p2 X1 = mk2(xv.y, xv.w);

        p2x2 wA = F4(0), wB = F4(2), wC = F4(4), wD = F4(6);
        p2x2 bA = F4(8), bB = F4(10);
        float lo, hi;
        p2 t, h0, h1, h2, h3;
        t = fma2(wA.a, X0, fma2(wA.b, X1, bA.a)); un2(t, lo, hi);
        h0 = mk2(fast_tanh(lo), fast_tanh(hi));
        t = fma2(wB.a, X0, fma2(wB.b, X1, bA.b)); un2(t, lo, hi);
        h1 = mk2(fast_tanh(lo), fast_tanh(hi));
        t = fma2(wC.a, X0, fma2(wC.b, X1, bB.a)); un2(t, lo, hi);
        h2 = mk2(fast_tanh(lo), fast_tanh(hi));
        t = fma2(wD.a, X0, fma2(wD.b, X1, bB.b)); un2(t, lo, hi);
        h3 = mk2(fast_tanh(lo), fast_tanh(hi));

        p2x2 r0a = F4(12), r0b = F4(14), r1a = F4(16), r1b = F4(18);
        p2x2 b2p = F4(20);
        p2 t0 = fma2(r0a.a, h0, fma2(r0a.b, h1, fma2(r0b.a, h2, fma2(r0b.b, h3, b2p.a))));
        p2 t1 = fma2(r1a.a, h0, fma2(r1a.b, h1, fma2(r1b.a, h2, fma2(r1b.b, h3, b2p.b))));

        float a0l, a0h, a1l, a1h;
        un2(t0, a0l, a0h); un2(t1, a1l, a1h);
        a0l = fast_tanh(a0l); a0h = fast_tanh(a0h);
        a1l = fast_tanh(a1l); a1h = fast_tanh(a1h);

        // FULL-angle sincos (basis is in a, not a/2)
        float sl, cl, sh, chh;
        __sincosf(a0l, &sl, &cl); __sincosf(a0h, &sh, &chh);
        build_u(u0[ch], mk2(cl, chh), mk2(sl, sh));
        __sincosf(a1l, &sl, &cl); __sincosf(a1h, &sh, &chh);
        build_u(u1[ch], mk2(cl, chh), mk2(sl, sh));
    }

    // y = u0^T W u1  (W columns contiguous: 4x LDS.128 + 1x LDS.64 per k)
    p2 y0, y1;
#pragma unroll
    for (int k = 0; k < 9; k++) {
        int e = WBASE(k);
        p2x2 w01 = F4(e), w23 = F4(e + 2), w45 = F4(e + 4), w67 = F4(e + 6);
        p2 w8 = C2[e + 8];
        p2 v0 = w01.a, v1 = w01.a;           // j=0 (B_0 = 1)
        v0 = fma2(w01.b, u0[0][0], v0);  v1 = fma2(w01.b, u0[1][0], v1);
        v0 = fma2(w23.a, u0[0][1], v0);  v1 = fma2(w23.a, u0[1][1], v1);
        v0 = fma2(w23.b, u0[0][2], v0);  v1 = fma2(w23.b, u0[1][2], v1);
        v0 = fma2(w45.a, u0[0][3], v0);  v1 = fma2(w45.a, u0[1][3], v1);
        v0 = fma2(w45.b, u0[0][4], v0);  v1 = fma2(w45.b, u0[1][4], v1);
        v0 = fma2(w67.a, u0[0][5], v0);  v1 = fma2(w67.a, u0[1][5], v1);
        v0 = fma2(w67.b, u0[0][6], v0);  v1 = fma2(w67.b, u0[1][6], v1);
        v0 = fma2(w8,    u0[0][7], v0);  v1 = fma2(w8,    u0[1][7], v1);
        if (k == 0) { y0 = v0; y1 = v1; }
        else {
            y0 = fma2(v0, u1[0][k - 1], y0);
            y1 = fma2(v1, u1[1][k - 1], y1);
        }
    }

    float yl, yh, o0, o1, o2, o3;
    un2(y0, yl, yh);
    o0 = fmaf(0.5f, fast_tanh(0.5f * yl), 0.5f);   // sigmoid(y) = 0.5 tanh(y/2) + 0.5
    o1 = fmaf(0.5f, fast_tanh(0.5f * yh), 0.5f);
    un2(y1, yl, yh);
    o2 = fmaf(0.5f, fast_tanh(0.5f * yl), 0.5f);
    o3 = fmaf(0.5f, fast_tanh(0.5f * yh), 0.5f);
    out4[i] = make_float4(o0, o1, o2, o3);
}

extern "C" void kernel_launch(void* const* d_in, const int* in_sizes, int n_in,
                              void* d_out, int out_size) {
    const float4* x  = (const float4*)d_in[0];
    const float* w1  = (const float*)d_in[1];
    const float* b1  = (const float*)d_in[2];
    const float* w2  = (const float*)d_in[3];
    const float* b2  = (const float*)d_in[4];
    const float* qw  = (const float*)d_in[5];
    const float* pw  = (const float*)d_in[6];
    const float* pb  = (const float*)d_in[7];
    float4* out = (float4*)d_out;

    setup_kernel<<<1, 128>>>(w1, b1, w2, b2, qw, pw, pb);

    int B4 = in_sizes[0] / 8;  // four samples per thread
    int grid = (B4 + TPB - 1) / TPB;
    hybrid_qnn_kernel<<<grid, TPB>>>(x, out, B4);
}

// round 12
// speedup vs baseline: 1.0107x; 1.0107x over previous
#include <cuda_runtime.h>

#define NL 4
#define TPB 128

typedef unsigned long long u64;

// ---- packed 2x f32 (Blackwell f32x2 pipe) ----
struct p2 { u64 v; };
struct p2x2 { p2 a, b; };

__device__ __forceinline__ p2 mk2(float lo, float hi) {
    p2 r; asm("mov.b64 %0, {%1,%2};" : "=l"(r.v) : "f"(lo), "f"(hi)); return r;
}
__device__ __forceinline__ void un2(p2 a, float& lo, float& hi) {
    asm("mov.b64 {%0,%1}, %2;" : "=f"(lo), "=f"(hi) : "l"(a.v));
}
__device__ __forceinline__ p2 fma2(p2 a, p2 b, p2 c) {
    p2 r; asm("fma.rn.f32x2 %0, %1, %2, %3;" : "=l"(r.v) : "l"(a.v), "l"(b.v), "l"(c.v)); return r;
}
__device__ __forceinline__ p2 mul2(p2 a, p2 b) {
    p2 r; asm("mul.rn.f32x2 %0, %1, %2;" : "=l"(r.v) : "l"(a.v), "l"(b.v)); return r;
}
__device__ __forceinline__ p2 add2(p2 a, p2 b) {
    p2 r; asm("add.rn.f32x2 %0, %1, %2;" : "=l"(r.v) : "l"(a.v), "l"(b.v)); return r;
}
__device__ __forceinline__ p2 neg2(p2 a) { p2 r; r.v = a.v ^ 0x8000000080000000ULL; return r; }

__device__ __forceinline__ float fast_tanh(float v) {
    float r; asm("tanh.approx.f32 %0, %1;" : "=f"(r) : "f"(v)); return r;
}

// ---- batch-invariant constants (written by block 0, read by all) ----
// float2 elements (both lanes equal), float4-friendly layout:
// [0:8) w1  [8:12) b1  [12:20) w2  [20:22) b2  [22:24) post_w  [24] post_b  [25] pad
// [26 + k*10 + j]  W(j,k), j=0..8 (+pad);  y(a0,a1) = sum_jk W(j,k) B_j(a0) B_k(a1)
//   basis: B_0=1, B_1=cos a, B_2=sin a, B_3=cos 2a, ... B_8=sin 4a
#define NC 116
__device__ __align__(16) float2 gStage[NC];
__device__ volatile int gFlag = 0;
__device__ unsigned int gDone = 0;
#define WBASE(k) (26 + (k) * 10)

// ---- scalar circuit helpers (setup phase only) ----
__device__ __forceinline__ void rx_s(float c, float s, float2& a, float2& b) {
    float2 na, nb;
    na.x = c * a.x + s * b.y; na.y = c * a.y - s * b.x;
    nb.x = c * b.x + s * a.y; nb.y = c * b.y - s * a.x;
    a = na; b = nb;
}
// SU(2): r00=(ar,ai), r01=(br,bi), r10=(-br,bi), r11=(ar,-ai)
__device__ __forceinline__ void rot_s(const float* M, float2& a, float2& b) {
    float ar = M[0], ai = M[1], br = M[2], bi = M[3];
    float2 na, nb;
    na.x = ar * a.x - ai * a.y + br * b.x - bi * b.y;
    na.y = ar * a.y + ai * a.x + br * b.y + bi * b.x;
    nb.x = -br * a.x - bi * a.y + ar * b.x + ai * b.y;
    nb.y = -br * a.y + bi * a.x + ar * b.y - ai * b.x;
    a = na; b = nb;
}

// u[0..7] = cos a, sin a, cos 2a, sin 2a, ..., cos 4a, sin 4a (packed, 2 samples)
__device__ __forceinline__ void build_u(p2* u, p2 c, p2 s) {
    u[0] = c; u[1] = s;
    p2 d = add2(c, c);
    u[2] = fma2(d, c, mk2(-1.f, -1.f));
    u[3] = mul2(d, s);
    u[4] = fma2(d, u[2], neg2(c));
    u[5] = fma2(d, u[3], neg2(s));
    u[6] = fma2(d, u[4], neg2(u[2]));
    u[7] = fma2(d, u[5], neg2(u[3]));
}

__global__ __launch_bounds__(TPB) void hybrid_qnn_kernel(
    const float4* __restrict__ x4, float4* __restrict__ out4, int B4,
    const float* __restrict__ w1, const float* __restrict__ b1,
    const float* __restrict__ w2, const float* __restrict__ b2,
    const float* __restrict__ qw,
    const float* __restrict__ pw, const float* __restrict__ pb)
{
    __shared__ float sM[8][4];      // setup: ar, ai, br, bi per Rot matrix
    __shared__ float sY[81];        // setup: y at grid nodes
    __shared__ float cT[9], sT[9];  // setup: cos/sin(2*pi*r/9) table
    __shared__ __align__(16) float2 sC[NC];
    int tid = threadIdx.x;
    const float TH = 6.2831853071795864769f / 9.0f;

    if (blockIdx.x == 0) {
        // ======== setup phase: compute gStage (done fresh every launch) ========
        if (tid < 25) {
            float v;
            if (tid < 8)       v = w1[tid];
            else if (tid < 12) v = b1[tid - 8];
            else if (tid < 20) v = w2[tid - 12];
            else if (tid < 22) v = b2[tid - 20];
            else if (tid < 24) v = pw[tid - 22];
            else               v = pb[0];
            gStage[tid] = make_float2(v, v);
        }
        if (tid >= 96 && tid < 105) gStage[WBASE(tid - 96) + 9] = make_float2(0.f, 0.f);
        if (tid == 105) gStage[25] = make_float2(0.f, 0.f);
        if (tid < 8) {
            const float* q = qw + tid * 3;
            float phi = q[0], th = q[1], om = q[2];
            float st, ct, sp, cp, sm, cm;
            sincosf(0.5f * th, &st, &ct);
            sincosf(0.5f * (phi + om), &sp, &cp);
            sincosf(0.5f * (phi - om), &sm, &cm);
            sM[tid][0] =  cp * ct;   // ar
            sM[tid][1] = -sp * ct;   // ai
            sM[tid][2] = -cm * st;   // br
            sM[tid][3] = -sm * st;   // bi
        }
        if (tid >= 32 && tid < 41) {
            int r = tid - 32;
            float sv, cv;
            sincosf(TH * (float)r, &sv, &cv);
            cT[r] = cv; sT[r] = sv;
        }
        __syncthreads();

        // simulate circuit at 81 grid nodes (exact bandlimited sampling)
        if (tid < 81) {
            int m = tid / 9, n = tid % 9;
            float c0, s0, c1, s1;
            __sincosf(0.5f * TH * (float)m, &s0, &c0);
            __sincosf(0.5f * TH * (float)n, &s1, &c1);
            float2 S00 = {1.f, 0.f}, S01 = {0.f, 0.f}, S10 = {0.f, 0.f}, S11 = {0.f, 0.f};
#pragma unroll
            for (int l = 0; l < NL; l++) {
                rx_s(c0, s0, S00, S10); rx_s(c0, s0, S01, S11);
                rx_s(c1, s1, S00, S01); rx_s(c1, s1, S10, S11);
                rot_s(sM[l * 2 + 0], S00, S10); rot_s(sM[l * 2 + 0], S01, S11);
                rot_s(sM[l * 2 + 1], S00, S01); rot_s(sM[l * 2 + 1], S10, S11);
                float2 t = S10; S10 = S11; S11 = t;   // CNOT(0,1)
                t = S01; S01 = S11; S11 = t;          // CNOT(1,0)
            }
            float p00 = S00.x * S00.x + S00.y * S00.y;
            float p01 = S01.x * S01.x + S01.y * S01.y;
            float p10 = S10.x * S10.x + S10.y * S10.y;
            float q0 = p00 + p01, q1 = p00 + p10;  // unitarity
            sY[tid] = pw[0] * q0 + pw[1] * q1 + pb[0];
        }
        __syncthreads();

        // exact DFT projection onto the 9x9 trig basis (table lookups only)
        if (tid < 81) {
            int j = tid / 9, k = tid % 9;
            int tjf = (j + 1) / 2, tkf = (k + 1) / 2;
            float tk[9];
#pragma unroll
            for (int n = 0; n < 9; n++) {
                if (k == 0) tk[n] = 1.0f / 9.0f;
                else {
                    int r = (n * tkf) % 9;
                    tk[n] = (2.0f / 9.0f) * ((k & 1) ? cT[r] : sT[r]);
                }
            }
            float acc = 0.f;
#pragma unroll
            for (int m = 0; m < 9; m++) {
                float tj;
                if (j == 0) tj = 1.0f / 9.0f;
                else {
                    int r = (m * tjf) % 9;
                    tj = (2.0f / 9.0f) * ((j & 1) ? cT[r] : sT[r]);
                }
                float inner = 0.f;
#pragma unroll
                for (int n = 0; n < 9; n++) inner += tk[n] * sY[m * 9 + n];
                acc += tj * inner;
            }
            gStage[WBASE(k) + j] = make_float2(acc, acc);
        }
        // publish: every writer fences, then one thread releases the flag
        __threadfence();
        __syncthreads();
        if (tid == 0) gFlag = 1;
    } else {
        // wait for block 0 to publish gStage
        if (tid == 0) {
            while (gFlag == 0) __nanosleep(64);
            __threadfence();
        }
        __syncthreads();
    }

    // per-launch reset by the LAST block to pass the gate (keeps every call
    // doing identical work: no cross-call caching)
    if (tid == 0) {
        unsigned int p = atomicAdd(&gDone, 1u);
        if (p == gridDim.x - 1) {
            gFlag = 0;
            __threadfence();
            gDone = 0;
        }
    }

    // ======== main phase ========
    if (tid < NC / 2) {   // 58 x LDG.128 / STS.128
        reinterpret_cast<float4*>(sC)[tid] =
            reinterpret_cast<const float4*>(gStage)[tid];
    }
    __syncthreads();

    int i = blockIdx.x * TPB + tid;
    if (i >= B4) return;

    const float4* C4 = reinterpret_cast<const float4*>(sC);
    const p2*     C2 = reinterpret_cast<const p2*>(sC);
    auto F4 = [&](int e) -> p2x2 {   // e must be even
        float4 t = C4[e >> 1];
        p2x2 r; r.a = mk2(t.x, t.y); r.b = mk2(t.z, t.w); return r;
    };

    // 4 samples per thread: 2 independent packed chains
    p2 u0[2][8], u1[2][8];
#pragma unroll
    for (int ch = 0; ch < 2; ch++) {
        float4 xv = x4[2 * i + ch];
        p2 X0 = mk2(xv.x, xv.z);
        p2 X1 = mk2(xv.y, xv.w);

        p2x2 wA = F4(0), wB = F4(2), wC = F4(4), wD = F4(6);
        p2x2 bA = F4(8), bB = F4(10);
        float lo, hi;
        p2 t, h0, h1, h2, h3;
        t = fma2(wA.a, X0, fma2(wA.b, X1, bA.a)); un2(t, lo, hi);
        h0 = mk2(fast_tanh(lo), fast_tanh(hi));
        t = fma2(wB.a, X0, fma2(wB.b, X1, bA.b)); un2(t, lo, hi);
        h1 = mk2(fast_tanh(lo), fast_tanh(hi));
        t = fma2(wC.a, X0, fma2(wC.b, X1, bB.a)); un2(t, lo, hi);
        h2 = mk2(fast_tanh(lo), fast_tanh(hi));
        t = fma2(wD.a, X0, fma2(wD.b, X1, bB.b)); un2(t, lo, hi);
        h3 = mk2(fast_tanh(lo), fast_tanh(hi));

        p2x2 r0a = F4(12), r0b = F4(14), r1a = F4(16), r1b = F4(18);
        p2x2 b2p = F4(20);
        p2 t0 = fma2(r0a.a, h0, fma2(r0a.b, h1, fma2(r0b.a, h2, fma2(r0b.b, h3, b2p.a))));
        p2 t1 = fma2(r1a.a, h0, fma2(r1a.b, h1, fma2(r1b.a, h2, fma2(r1b.b, h3, b2p.b))));

        float a0l, a0h, a1l, a1h;
        un2(t0, a0l, a0h); un2(t1, a1l, a1h);
        a0l = fast_tanh(a0l); a0h = fast_tanh(a0h);
        a1l = fast_tanh(a1l); a1h = fast_tanh(a1h);

        float sl, cl, sh, chh;
        __sincosf(a0l, &sl, &cl); __sincosf(a0h, &sh, &chh);
        build_u(u0[ch], mk2(cl, chh), mk2(sl, sh));
        __sincosf(a1l, &sl, &cl); __sincosf(a1h, &sh, &chh);
        build_u(u1[ch], mk2(cl, chh), mk2(sl, sh));
    }

    // y = u0^T W u1  (W columns contiguous: 4x LDS.128 + 1x LDS.64 per k)
    p2 y0, y1;
#pragma unroll
    for (int k = 0; k < 9; k++) {
        int e = WBASE(k);
        p2x2 w01 = F4(e), w23 = F4(e + 2), w45 = F4(e + 4), w67 = F4(e + 6);
        p2 w8 = C2[e + 8];
        p2 v0 = w01.a, v1 = w01.a;           // j=0 (B_0 = 1)
        v0 = fma2(w01.b, u0[0][0], v0);  v1 = fma2(w01.b, u0[1][0], v1);
        v0 = fma2(w23.a, u0[0][1], v0);  v1 = fma2(w23.a, u0[1][1], v1);
        v0 = fma2(w23.b, u0[0][2], v0);  v1 = fma2(w23.b, u0[1][2], v1);
        v0 = fma2(w45.a, u0[0][3], v0);  v1 = fma2(w45.a, u0[1][3], v1);
        v0 = fma2(w45.b, u0[0][4], v0);  v1 = fma2(w45.b, u0[1][4], v1);
        v0 = fma2(w67.a, u0[0][5], v0);  v1 = fma2(w67.a, u0[1][5], v1);
        v0 = fma2(w67.b, u0[0][6], v0);  v1 = fma2(w67.b, u0[1][6], v1);
        v0 = fma2(w8,    u0[0][7], v0);  v1 = fma2(w8,    u0[1][7], v1);
        if (k == 0) { y0 = v0; y1 = v1; }
        else {
            y0 = fma2(v0, u1[0][k - 1], y0);
            y1 = fma2(v1, u1[1][k - 1], y1);
        }
    }

    float yl, yh, o0, o1, o2, o3;
    un2(y0, yl, yh);
    o0 = fmaf(0.5f, fast_tanh(0.5f * yl), 0.5f);   // sigmoid(y) = 0.5 tanh(y/2) + 0.5
    o1 = fmaf(0.5f, fast_tanh(0.5f * yh), 0.5f);
    un2(y1, yl, yh);
    o2 = fmaf(0.5f, fast_tanh(0.5f * yl), 0.5f);
    o3 = fmaf(0.5f, fast_tanh(0.5f * yh), 0.5f);
    out4[i] = make_float4(o0, o1, o2, o3);
}

extern "C" void kernel_launch(void* const* d_in, const int* in_sizes, int n_in,
                              void* d_out, int out_size) {
    const float4* x  = (const float4*)d_in[0];
    const float* w1  = (const float*)d_in[1];
    const float* b1  = (const float*)d_in[2];
    const float* b1b = (const float*)d_in[2];
    const float* w2  = (const float*)d_in[3];
    const float* b2  = (const float*)d_in[4];
    const float* qw  = (const float*)d_in[5];
    const float* pw  = (const float*)d_in[6];
    const float* pb  = (const float*)d_in[7];
    (void)b1b;
    float4* out = (float4*)d_out;

    int B4 = in_sizes[0] / 8;  // four samples per thread
    int grid = (B4 + TPB - 1) / TPB;
    hybrid_qnn_kernel<<<grid, TPB>>>(x, out, B4, w1, b1, w2, b2, qw, pw, pb);
}